// round 12
// baseline (speedup 1.0000x reference)
#include <cuda_runtime.h>
#include <cuda_bf16.h>
#include <cstdint>

// out[b] = (X X^T) X == X (X^T X);  G = X^T X is 128x128 per batch, symmetric.
// R12: 64-row chunks, grid 256, 256 threads -> ~2 resident CTAs/SM so fill /
// epilogue / stall latency of one CTA hides under the other's mainloop.
// (R4/R6/R10/R11 showed the syrk floor is invariant to intra-CTA changes.)

#define NB     4
#define TT     4096
#define DD     128
#define SPLITS 64
#define CHUNK  64
#define PB     136   // bf16 pitch: 272B; 272 mod 128 == 16 -> ldmatrix conflict-free

__device__ float g_partial[NB * SPLITS * DD * DD];  // 16 MB (upper blocks valid)
__device__ float g_G[NB * DD * DD];                 // 256 KB

__device__ __forceinline__ uint32_t smem_u32(const void* p) {
    uint32_t a;
    asm("{ .reg .u64 t; cvta.to.shared.u64 t, %1; cvt.u32.u64 %0, t; }" : "=r"(a) : "l"(p));
    return a;
}

__device__ __forceinline__ void ldm_x4(uint32_t* r, uint32_t addr) {
    asm volatile("ldmatrix.sync.aligned.m8n8.x4.shared.b16 {%0,%1,%2,%3}, [%4];"
                 : "=r"(r[0]), "=r"(r[1]), "=r"(r[2]), "=r"(r[3]) : "r"(addr));
}

__device__ __forceinline__ void ldm_x4_t(uint32_t* r, uint32_t addr) {
    asm volatile("ldmatrix.sync.aligned.m8n8.x4.trans.shared.b16 {%0,%1,%2,%3}, [%4];"
                 : "=r"(r[0]), "=r"(r[1]), "=r"(r[2]), "=r"(r[3]) : "r"(addr));
}

__device__ __forceinline__ void ldm_x2_t(uint32_t* r, uint32_t addr) {
    asm volatile("ldmatrix.sync.aligned.m8n8.x2.trans.shared.b16 {%0,%1}, [%2];"
                 : "=r"(r[0]), "=r"(r[1]) : "r"(addr));
}

__device__ __forceinline__ void mma_bf16(float* d, const uint32_t* a, uint32_t b0, uint32_t b1) {
    asm volatile(
        "mma.sync.aligned.m16n8k16.row.col.f32.bf16.bf16.f32 "
        "{%0,%1,%2,%3}, {%4,%5,%6,%7}, {%8,%9}, {%0,%1,%2,%3};"
        : "+f"(d[0]), "+f"(d[1]), "+f"(d[2]), "+f"(d[3])
        : "r"(a[0]), "r"(a[1]), "r"(a[2]), "r"(a[3]), "r"(b0), "r"(b1));
}

__device__ __forceinline__ void split_bf16(float v, __nv_bfloat16& h, __nv_bfloat16& l) {
    h = __float2bfloat16_rn(v);
    l = __float2bfloat16_rn(v - __bfloat162float(h));
}

__device__ __forceinline__ void split4_pack(float4 v, uint2& hp, uint2& lp) {
    __nv_bfloat16 hx, lx, hy, ly, hz, lz, hw, lw;
    split_bf16(v.x, hx, lx); split_bf16(v.y, hy, ly);
    split_bf16(v.z, hz, lz); split_bf16(v.w, hw, lw);
    __nv_bfloat162 h01(hx, hy), h23(hz, hw), l01(lx, ly), l23(lz, lw);
    hp.x = *reinterpret_cast<uint32_t*>(&h01);
    hp.y = *reinterpret_cast<uint32_t*>(&h23);
    lp.x = *reinterpret_cast<uint32_t*>(&l01);
    lp.y = *reinterpret_cast<uint32_t*>(&l23);
}

// ---------------------------------------------------------------------------
// Kernel 1: upper triangle of P[b,s] = Xc^T * Xc for a 64-row chunk.
// 256 threads / 8 warps; 40 blocks of 32(d1) x 8(d2) with c0 >= 32*ti:
//   w0: ti0 c0=0   nb=6 | w1: ti0 c0=48 nb=5 | w2: ti0 c0=88 nb=5
//   w3: ti1 c0=32  nb=6 | w4: ti1 c0=80 nb=6
//   w5: ti2 c0=64  nb=4 | w6: ti2 c0=96 nb=4 | w7: ti3 c0=96 nb=4
// ---------------------------------------------------------------------------
__global__ void __launch_bounds__(256, 1)
syrk_kernel(const float* __restrict__ x)
{
    extern __shared__ char smc[];
    __nv_bfloat16* Hi = reinterpret_cast<__nv_bfloat16*>(smc);   // [64 t][PB d]
    __nv_bfloat16* Lo = Hi + CHUNK * PB;

    const int s = blockIdx.x, b = blockIdx.y;
    const int tid = threadIdx.x, lane = tid & 31, w = tid >> 5;

    const float4* xg = reinterpret_cast<const float4*>(
        x + ((size_t)b * TT + (size_t)s * CHUNK) * DD);

    // Row-major fill (2048 float4 over 256 threads).
#pragma unroll
    for (int j = 0; j < 8; j++) {
        const int idx = tid + j * 256;
        const int t = idx >> 5, kq = idx & 31;
        uint2 hp, lp;
        split4_pack(xg[idx], hp, lp);
        *reinterpret_cast<uint2*>(Hi + t * PB + 4 * kq) = hp;
        *reinterpret_cast<uint2*>(Lo + t * PB + 4 * kq) = lp;
    }
    __syncthreads();

    int ti, c0, nb;
    switch (w) {
        case 0:  ti = 0; c0 = 0;  nb = 6; break;
        case 1:  ti = 0; c0 = 48; nb = 5; break;
        case 2:  ti = 0; c0 = 88; nb = 5; break;
        case 3:  ti = 1; c0 = 32; nb = 6; break;
        case 4:  ti = 1; c0 = 80; nb = 6; break;
        case 5:  ti = 2; c0 = 64; nb = 4; break;
        case 6:  ti = 2; c0 = 96; nb = 4; break;
        default: ti = 3; c0 = 96; nb = 4; break;
    }
    const int m0 = ti * 32;

    const int gr = lane >> 2;
    const int gc = lane & 3;

    const uint32_t hiB = smem_u32(Hi);
    const uint32_t loB = smem_u32(Lo);
    const uint32_t trow = (uint32_t)((lane & 7) + ((lane >> 4) << 3));
    const uint32_t tcol = (uint32_t)(((lane >> 3) & 1) << 3);
    const uint32_t t2row = (uint32_t)(lane & 15);

    float acc[6][2][4];
#pragma unroll
    for (int j = 0; j < 6; j++)
#pragma unroll
        for (int mt = 0; mt < 2; mt++)
#pragma unroll
            for (int q = 0; q < 4; q++) acc[j][mt][q] = 0.0f;

#pragma unroll
    for (int k0 = 0; k0 < CHUNK; k0 += 16) {
        uint32_t ah[2][4], al[2][4];
#pragma unroll
        for (int mt = 0; mt < 2; mt++) {
            uint32_t off = (((uint32_t)k0 + trow) * PB + (uint32_t)(m0 + mt * 16) + tcol) * 2;
            ldm_x4_t(ah[mt], hiB + off);
            ldm_x4_t(al[mt], loB + off);
        }
        uint32_t bh[3][4], bl[3][4];
#pragma unroll
        for (int jb = 0; jb < 3; jb++) {
            const int cb = c0 + jb * 16;
            if (2 * jb + 1 < nb) {
                uint32_t off = (((uint32_t)k0 + trow) * PB + (uint32_t)cb + tcol) * 2;
                ldm_x4_t(bh[jb], hiB + off);
                ldm_x4_t(bl[jb], loB + off);
            } else if (2 * jb < nb) {
                uint32_t off = (((uint32_t)k0 + t2row) * PB + (uint32_t)cb) * 2;
                ldm_x2_t(bh[jb], hiB + off);
                ldm_x2_t(bl[jb], loB + off);
            }
        }
#pragma unroll
        for (int jb = 0; jb < 3; jb++) {
            if (2 * jb + 1 < nb) {
#pragma unroll
                for (int sub = 0; sub < 2; sub++) {
                    const int j = 2 * jb + sub;
#pragma unroll
                    for (int mt = 0; mt < 2; mt++) {
                        mma_bf16(acc[j][mt], ah[mt], bh[jb][sub], bh[jb][sub + 2]);
                        mma_bf16(acc[j][mt], ah[mt], bl[jb][sub], bl[jb][sub + 2]);
                        mma_bf16(acc[j][mt], al[mt], bh[jb][sub], bh[jb][sub + 2]);
                    }
                }
            } else if (2 * jb < nb) {
                const int j = 2 * jb;
#pragma unroll
                for (int mt = 0; mt < 2; mt++) {
                    mma_bf16(acc[j][mt], ah[mt], bh[jb][0], bh[jb][1]);
                    mma_bf16(acc[j][mt], ah[mt], bl[jb][0], bl[jb][1]);
                    mma_bf16(acc[j][mt], al[mt], bh[jb][0], bh[jb][1]);
                }
            }
        }
    }

    float* outp = g_partial + (size_t)(b * SPLITS + s) * DD * DD;
#pragma unroll
    for (int j = 0; j < 6; j++) {
        if (j < nb) {
#pragma unroll
            for (int mt = 0; mt < 2; mt++) {
                const int row = m0 + mt * 16 + gr;
                const int col = c0 + j * 8 + 2 * gc;
                *reinterpret_cast<float2*>(outp + row * DD + col) =
                    make_float2(acc[j][mt][0], acc[j][mt][1]);
                *reinterpret_cast<float2*>(outp + (row + 8) * DD + col) =
                    make_float2(acc[j][mt][2], acc[j][mt][3]);
            }
        }
    }
}

// ---------------------------------------------------------------------------
// Kernel 2: G[b] = sum_s P[b,s] (upper-only, coalesced float4) + mirror.
// One warp per (b, d1) row; lane = quad column kq.
// ---------------------------------------------------------------------------
__global__ void __launch_bounds__(128, 1)
reduce_kernel()
{
    const int gw  = blockIdx.x * 4 + (threadIdx.x >> 5);  // 0..511
    const int lane = threadIdx.x & 31;
    const int b   = gw >> 7;
    const int d1  = gw & 127;
    const int kq  = lane;

    if (4 * kq + 3 < d1) return;

    const float4* base = reinterpret_cast<const float4*>(g_partial)
                       + (size_t)b * SPLITS * 4096 + d1 * 32 + kq;
    float4 acc = make_float4(0.f, 0.f, 0.f, 0.f);
#pragma unroll
    for (int s = 0; s < SPLITS; s++) {
        float4 v = base[(size_t)s * 4096];
        acc.x += v.x; acc.y += v.y; acc.z += v.z; acc.w += v.w;
    }

    float* gb = g_G + (size_t)b * 16384;
    *reinterpret_cast<float4*>(gb + d1 * 128 + 4 * kq) = acc;

    const float vv[4] = {acc.x, acc.y, acc.z, acc.w};
#pragma unroll
    for (int i = 0; i < 4; i++) {
        const int c = 4 * kq + i;
        if (c > d1) gb[c * 128 + d1] = vv[i];
    }
}

// ---------------------------------------------------------------------------
// Kernel 3: out_chunk(64 rows) = Xc * G[b].  256 threads / 8 warps, 16x64 tile
// per warp (wm = w>>1, wn = w&1). A = Xc row-major; B = G row-major (symmetric).
// ---------------------------------------------------------------------------
__global__ void __launch_bounds__(256, 1)
gemm_kernel(const float* __restrict__ x, float* __restrict__ out)
{
    extern __shared__ char smc[];
    __nv_bfloat16* Ghi = reinterpret_cast<__nv_bfloat16*>(smc);      // [128][PB]
    __nv_bfloat16* Glo = Ghi + DD * PB;
    __nv_bfloat16* Xhi = Glo + DD * PB;                              // [64][PB]
    __nv_bfloat16* Xlo = Xhi + CHUNK * PB;

    const int s = blockIdx.x, b = blockIdx.y;
    const int tid = threadIdx.x, lane = tid & 31, w = tid >> 5;

    const float4* xg = reinterpret_cast<const float4*>(
        x + ((size_t)b * TT + (size_t)s * CHUNK) * DD);
    const float4* gg = reinterpret_cast<const float4*>(g_G + (size_t)b * DD * DD);

    // Fill G (4096 float4) and X (2048 float4).
#pragma unroll
    for (int j = 0; j < 16; j++) {
        const int idx = tid + j * 256;
        const int r = idx >> 5, kq = idx & 31;
        uint2 hp, lp;
        split4_pack(gg[idx], hp, lp);
        *reinterpret_cast<uint2*>(Ghi + r * PB + 4 * kq) = hp;
        *reinterpret_cast<uint2*>(Glo + r * PB + 4 * kq) = lp;
    }
#pragma unroll
    for (int j = 0; j < 8; j++) {
        const int idx = tid + j * 256;
        const int t = idx >> 5, kq = idx & 31;
        uint2 hp, lp;
        split4_pack(xg[idx], hp, lp);
        *reinterpret_cast<uint2*>(Xhi + t * PB + 4 * kq) = hp;
        *reinterpret_cast<uint2*>(Xlo + t * PB + 4 * kq) = lp;
    }
    __syncthreads();

    const int m0 = (w >> 1) * 16;
    const int n0 = (w & 1) * 64;
    const int gr = lane >> 2;
    const int gc = lane & 3;

    const uint32_t xhB = smem_u32(Xhi);
    const uint32_t xlB = smem_u32(Xlo);
    const uint32_t ghB = smem_u32(Ghi);
    const uint32_t glB = smem_u32(Glo);
    const uint32_t lrow = (uint32_t)(lane & 15);
    const uint32_t lkof = (uint32_t)((lane >> 4) << 3);

    float acc[8][4];
#pragma unroll
    for (int nt = 0; nt < 8; nt++)
#pragma unroll
        for (int q = 0; q < 4; q++) acc[nt][q] = 0.0f;

#pragma unroll
    for (int k0 = 0; k0 < 128; k0 += 16) {
        uint32_t ah[4], al[4];
        {
            uint32_t off = (((uint32_t)m0 + lrow) * PB + (uint32_t)k0 + lkof) * 2;
            ldm_x4(ah, xhB + off);
            ldm_x4(al, xlB + off);
        }
#pragma unroll
        for (int ng = 0; ng < 4; ng++) {
            uint32_t bh[4], bl[4];
            uint32_t off = (((uint32_t)(n0 + ng * 16) + lrow) * PB + (uint32_t)k0 + lkof) * 2;
            ldm_x4(bh, ghB + off);
            ldm_x4(bl, glB + off);
#pragma unroll
            for (int sub = 0; sub < 2; sub++) {
                const int nt = ng * 2 + sub;
                mma_bf16(acc[nt], ah, bh[sub], bh[sub + 2]);
                mma_bf16(acc[nt], ah, bl[sub], bl[sub + 2]);
                mma_bf16(acc[nt], al, bh[sub], bh[sub + 2]);
            }
        }
    }

    float* ob = out + ((size_t)b * TT + (size_t)s * CHUNK) * DD;
#pragma unroll
    for (int nt = 0; nt < 8; nt++) {
        const int row = m0 + gr;
        const int col = n0 + nt * 8 + 2 * gc;
        *reinterpret_cast<float2*>(ob + row * DD + col) =
            make_float2(acc[nt][0], acc[nt][1]);
        *reinterpret_cast<float2*>(ob + (row + 8) * DD + col) =
            make_float2(acc[nt][2], acc[nt][3]);
    }
}

// ---------------------------------------------------------------------------

extern "C" void kernel_launch(void* const* d_in, const int* in_sizes, int n_in,
                              void* d_out, int out_size)
{
    (void)in_sizes; (void)n_in; (void)out_size;
    const float* x = (const float*)d_in[0];
    float* out = (float*)d_out;

    const int smem1 = 2 * CHUNK * PB * 2;                 // 34816 B
    const int smem3 = 2 * DD * PB * 2 + 2 * CHUNK * PB * 2;  // 104448 B

    cudaFuncSetAttribute(syrk_kernel, cudaFuncAttributeMaxDynamicSharedMemorySize, smem1);
    cudaFuncSetAttribute(gemm_kernel, cudaFuncAttributeMaxDynamicSharedMemorySize, smem3);

    syrk_kernel<<<dim3(SPLITS, NB), 256, smem1>>>(x);
    reduce_kernel<<<128, 128>>>();
    gemm_kernel<<<dim3(SPLITS, NB), 256, smem3>>>(x, out);
}